// round 7
// baseline (speedup 1.0000x reference)
#include <cuda_runtime.h>
#include <cstdint>

// LengthRegulator: expand hidden_phonems [B,L,D] by durations [B,L] into
// out [B, max_T, D], zero-padded beyond totals[b].
//
// R7: barrier-free single kernel. Each block (256 thr) = 4 phonemes of one
// batch; each warp independently computes (batch_total, prefix(my phoneme))
// by loading all 512 durations (4 coalesced int4 LDG, L1-hit) and doing ONE
// packed butterfly reduction -- no smem, no __syncthreads. Row LDG is issued
// before the reduction to hide its latency. Store loop has EXACT trip count d
// (R5/R6 issued 7 predicated STG.128 slots at ~12cyc each regardless of d --
// that dead issue was ~5us chip-wide).

#define B_CONST 32
#define L_CONST 512
#define D_CONST 256
#define D4 (D_CONST / 4)
#define MAX_DUR 8
#define P_PER_BLK 4
#define BLOCKS_PER_BATCH (L_CONST / P_PER_BLK)   // 128

__global__ void __launch_bounds__(256) lr_fused(
    const float4* __restrict__ hidden4,
    const int*    __restrict__ durations,
    float4*       __restrict__ out4,
    int max_T)
{
    const int t        = threadIdx.x;            // 0..255
    const int blk      = blockIdx.x;             // 0..4095
    const int b        = blk >> 7;               // batch
    const int blkLocal = blk & (BLOCKS_PER_BATCH - 1);
    const int l0       = blkLocal * P_PER_BLK;
    const int fgrp     = t >> 6;                 // phoneme within block [0,4)
    const int lane64   = t & 63;                 // float4 lane over D
    const int lp       = l0 + fgrp;              // my phoneme

    // ---- issue the row load FIRST; latency hides under the reduction below
    const float4 v = hidden4[((size_t)b * L_CONST + lp) * D4 + lane64];

    const int* __restrict__ dbat = durations + b * L_CONST;
    const int lane = t & 31;

    // ---- per-warp packed reduction over all 512 durations:
    //      low 16 bits = batch total, high 16 bits = exclusive prefix(lp)
    int packed = 0;
    #pragma unroll
    for (int q = 0; q < 4; ++q) {
        const int i = q * 128 + lane * 4;        // quad start (multiple of 4)
        int4 dd = *(const int4*)(dbat + i);      // coalesced 512B per warp-LDG
        const int full = dd.x + dd.y + dd.z + dd.w;
        int c;
        if (i + 4 <= lp)      c = full;          // quad fully before lp
        else if (i >= lp)     c = 0;             // quad fully at/after lp
        else {                                   // straddling quad
            const int k = lp - i;                // 1..3
            c = dd.x + ((k > 1) ? dd.y : 0) + ((k > 2) ? dd.z : 0);
        }
        packed += full + (c << 16);
    }
    #pragma unroll
    for (int o = 16; o > 0; o >>= 1)
        packed += __shfl_xor_sync(0xffffffffu, packed, o);

    const int total = packed & 0xFFFF;
    const int start = packed >> 16;              // exclusive prefix at lp
    const int d     = dbat[lp];                  // warp-uniform L1-hit scalar

    // ---- exact-trip replication: d warp-uniform coalesced STG.128
    float4* dst = out4 + ((size_t)b * max_T + start) * D4 + lane64;
    for (int j = 0; j < d; ++j)
        dst[j * D4] = v;

    // ---- tail zeroing: this block's strided share of [total, max_T)
    const float4 zero = make_float4(0.f, 0.f, 0.f, 0.f);
    for (int f = total + blkLocal * 4 + fgrp; f < max_T; f += 4 * BLOCKS_PER_BATCH) {
        out4[((size_t)b * max_T + f) * D4 + lane64] = zero;
    }
}

extern "C" void kernel_launch(void* const* d_in, const int* in_sizes, int n_in,
                              void* d_out, int out_size) {
    const float* hidden    = (const float*)d_in[0];   // [B, L, D] fp32
    const int*   durations = (const int*)d_in[1];     // [B, L] int32
    float*       out       = (float*)d_out;

    const int max_T = out_size / (B_CONST * D_CONST);

    lr_fused<<<B_CONST * BLOCKS_PER_BATCH, 256>>>(
        (const float4*)hidden, durations, (float4*)out, max_T);
}